// round 5
// baseline (speedup 1.0000x reference)
#include <cuda_runtime.h>
#include <cuda_bf16.h>
#include <math.h>

// ---------------------------------------------------------------------------
// Problem constants
// ---------------------------------------------------------------------------
#define BB   8
#define LL   4096
#define BL   (BB*LL)        // 32768
#define DD   512
#define CC   256
#define TT   2
#define HH   2
#define HDD  256
#define HC   512
#define H2   1024
#define LN_EPS 1e-5f

// ---------------------------------------------------------------------------
// Scratch (device globals; no runtime allocation allowed).
// NOTE: these symbols are NEVER passed as kernel arguments from host code
// (host-side symbol decay gives the host shadow address, which on GB300/ATS
// silently reads host memory). Kernels resolve them via gsel(id) device-side.
// ---------------------------------------------------------------------------
__device__ float g_gb[BB*1024];        // 1: gamma|beta  (film)
__device__ float g_gate[BB*DD];        // 2: sigmoid gate
__device__ float g_h[BB*HC];           // 3: gelu(ctx @ w1)
__device__ float g_ctxadd[BB*DD];      // 4: ctx @ concat_w[:,D:].T + concat_b
__device__ float g_ctxtok[BB*TT*DD];   // 5
__device__ float g_k[BB*TT*DD];        // 6
__device__ float g_v[BB*TT*DD];        // 7
__device__ float g_base[(size_t)BL*DD];// 8
__device__ float g_xq[(size_t)BL*DD];  // 9: x_q, later reused for attention out
__device__ float g_q[(size_t)BL*DD];   // 10
__device__ float g_updc[(size_t)BL*DD];// 11
__device__ float g_ao[(size_t)BL*DD];  // 12
__device__ float g_mixh[(size_t)BL*H2];// 13
__device__ float g_upda[(size_t)BL*DD];// 14
__device__ float g_w1c[1024*1536];     // 15: combined mix_w1
__device__ int   g_maskmode;           // 0 = 4-byte words, 1 = bytes (bool)

// Device-side resolver: id>0 selects a scratch global; id==0 uses the passed
// pointer (a real device pointer from d_in/d_out).
__device__ __forceinline__ float* gsel(const float* p, int id)
{
    switch (id) {
        case 1:  return g_gb;
        case 2:  return g_gate;
        case 3:  return g_h;
        case 4:  return g_ctxadd;
        case 5:  return g_ctxtok;
        case 6:  return g_k;
        case 7:  return g_v;
        case 8:  return g_base;
        case 9:  return g_xq;
        case 10: return g_q;
        case 11: return g_updc;
        case 12: return g_ao;
        case 13: return g_mixh;
        case 14: return g_upda;
        case 15: return g_w1c;
        default: return const_cast<float*>(p);
    }
}

// ---------------------------------------------------------------------------
// Mask dtype detection (robust to uint8 bool / int32 / float32 encodings).
// ---------------------------------------------------------------------------
__global__ void detect_mask_kernel(const unsigned char* __restrict__ m)
{
    __shared__ int s_gt1, s_odd;
    if (threadIdx.x == 0) { s_gt1 = 0; s_odd = 0; }
    __syncthreads();
    int lgt1 = 0, lodd = 0;
    for (int i = threadIdx.x; i < BL; i += 256) {
        unsigned char v = m[i];
        if (v > 1) lgt1 = 1;
        if ((i & 3) && v) lodd = 1;
    }
    if (lgt1) atomicOr(&s_gt1, 1);
    if (lodd) atomicOr(&s_odd, 1);
    __syncthreads();
    if (threadIdx.x == 0)
        g_maskmode = (!s_gt1 && s_odd) ? 1 : 0;
}

// ---------------------------------------------------------------------------
// Small GEMM: out[m,n] = act( sum_k A[m,k]*W[n,k] + bias[n] )
// act: 0 none, 1 gelu(exact), 2 sigmoid
// ---------------------------------------------------------------------------
__global__ void small_gemm(const float* __restrict__ Ap, int Aid, int lda,
                           const float* __restrict__ W, int ldw,
                           const float* __restrict__ bias,
                           int outid,
                           int M, int N, int K, int act)
{
    const float* A = gsel(Ap, Aid);
    float* out = gsel(nullptr, outid);
    int i = blockIdx.x * blockDim.x + threadIdx.x;
    if (i >= M * N) return;
    int m = i / N, n = i % N;
    const float* a = A + (size_t)m * lda;
    const float* w = W + (size_t)n * ldw;
    float s = 0.f;
    for (int k = 0; k < K; k++) s += a[k] * w[k];
    s += bias[n];
    if (act == 1) s = 0.5f * s * (1.f + erff(s * 0.70710678118654752f));
    else if (act == 2) s = 1.f / (1.f + expf(-s));
    out[i] = s;
}

// ---------------------------------------------------------------------------
// Build combined mix_w1:  W1c[n, 0:512]=Wa+Wc, [512:1024]=Wb-Wc, [1024:1536]=Wd
// ---------------------------------------------------------------------------
__global__ void prep_w1c(const float* __restrict__ mw1)
{
    int i = blockIdx.x * blockDim.x + threadIdx.x;
    if (i >= 1024 * 1536) return;
    int n = i / 1536, k = i % 1536;
    const float* r = mw1 + (size_t)n * 2048;
    float v;
    if      (k < 512)  v = r[k] + r[k + 1024];
    else if (k < 1024) v = r[k] - r[k + 512];
    else               v = r[k + 512];
    g_w1c[i] = v;
}

// ---------------------------------------------------------------------------
// Block reduce (128 threads) of two sums
// ---------------------------------------------------------------------------
__device__ __forceinline__ float2 block_reduce2_128(float a, float b)
{
    __shared__ float sa[4], sb[4];
    int lane = threadIdx.x & 31, w = threadIdx.x >> 5;
    #pragma unroll
    for (int o = 16; o; o >>= 1) {
        a += __shfl_down_sync(0xffffffffu, a, o);
        b += __shfl_down_sync(0xffffffffu, b, o);
    }
    if (lane == 0) { sa[w] = a; sb[w] = b; }
    __syncthreads();
    return make_float2(sa[0] + sa[1] + sa[2] + sa[3],
                       sb[0] + sb[1] + sb[2] + sb[3]);
}

// ---------------------------------------------------------------------------
// Row LN of x -> base (film) and x_q (q_ln) in one pass
// ---------------------------------------------------------------------------
__global__ void ln_base_kernel(const float* __restrict__ x,
                               const float* __restrict__ fg, const float* __restrict__ fb,
                               const float* __restrict__ qg, const float* __restrict__ qb)
{
    int row = blockIdx.x;
    int b = row >> 12;  // /4096
    const float* xr = x + (size_t)row * DD;
    float v[4], s = 0.f, s2 = 0.f;
    #pragma unroll
    for (int i = 0; i < 4; i++) {
        v[i] = xr[threadIdx.x + i * 128];
        s += v[i]; s2 += v[i] * v[i];
    }
    float2 r = block_reduce2_128(s, s2);
    float mean = r.x * (1.f / DD);
    float var  = r.y * (1.f / DD) - mean * mean;
    float inv  = rsqrtf(var + LN_EPS);
    #pragma unroll
    for (int i = 0; i < 4; i++) {
        int d = threadIdx.x + i * 128;
        float xh = (v[i] - mean) * inv;
        float lnf = xh * fg[d] + fb[d];
        float ga = g_gb[b * 1024 + d];
        float be = g_gb[b * 1024 + 512 + d];
        g_base[(size_t)row * DD + d] = (1.f + ga) * lnf + be;
        g_xq [(size_t)row * DD + d] = xh * qg[d] + qb[d];
    }
}

// ---------------------------------------------------------------------------
// In-place row LN of g_updc
// ---------------------------------------------------------------------------
__global__ void ln_updc_kernel(const float* __restrict__ g, const float* __restrict__ b)
{
    int row = blockIdx.x;
    float* sr = g_updc + (size_t)row * DD;
    float v[4], s = 0.f, s2 = 0.f;
    #pragma unroll
    for (int i = 0; i < 4; i++) {
        v[i] = sr[threadIdx.x + i * 128];
        s += v[i]; s2 += v[i] * v[i];
    }
    float2 r = block_reduce2_128(s, s2);
    float mean = r.x * (1.f / DD);
    float var  = r.y * (1.f / DD) - mean * mean;
    float inv  = rsqrtf(var + LN_EPS);
    #pragma unroll
    for (int i = 0; i < 4; i++) {
        int d = threadIdx.x + i * 128;
        sr[d] = (v[i] - mean) * inv * g[d] + b[d];
    }
}

// ---------------------------------------------------------------------------
// Attention: T=2 keys, H=2 heads, HD=256. Writes 'a' into g_xq (reuse).
// ---------------------------------------------------------------------------
__global__ void attn_kernel()
{
    int row = blockIdx.x;
    int b = row >> 12;
    int tid = threadIdx.x;
    const float* qr = g_q + (size_t)row * DD;
    const float* kb = g_k + b * (TT * DD);
    const float* vb = g_v + b * (TT * DD);

    float a00 = 0, a01 = 0, a10 = 0, a11 = 0;   // [h][t]
    {
        int d0 = tid, d1 = tid + 128, d2 = tid + 256, d3 = tid + 384;
        float q0 = qr[d0], q1 = qr[d1], q2 = qr[d2], q3 = qr[d3];
        a00 += q0 * kb[d0] + q1 * kb[d1];
        a01 += q0 * kb[512 + d0] + q1 * kb[512 + d1];
        a10 += q2 * kb[d2] + q3 * kb[d3];
        a11 += q2 * kb[512 + d2] + q3 * kb[512 + d3];
    }
    __shared__ float red[4][4];
    int lane = tid & 31, w = tid >> 5;
    #pragma unroll
    for (int o = 16; o; o >>= 1) {
        a00 += __shfl_down_sync(0xffffffffu, a00, o);
        a01 += __shfl_down_sync(0xffffffffu, a01, o);
        a10 += __shfl_down_sync(0xffffffffu, a10, o);
        a11 += __shfl_down_sync(0xffffffffu, a11, o);
    }
    if (lane == 0) { red[w][0] = a00; red[w][1] = a01; red[w][2] = a10; red[w][3] = a11; }
    __syncthreads();
    float s00 = (red[0][0] + red[1][0] + red[2][0] + red[3][0]) * 0.0625f; // /sqrt(256)
    float s01 = (red[0][1] + red[1][1] + red[2][1] + red[3][1]) * 0.0625f;
    float s10 = (red[0][2] + red[1][2] + red[2][2] + red[3][2]) * 0.0625f;
    float s11 = (red[0][3] + red[1][3] + red[2][3] + red[3][3]) * 0.0625f;

    float m0 = fmaxf(s00, s01);
    float e0a = expf(s00 - m0), e0b = expf(s01 - m0);
    float p00 = e0a / (e0a + e0b), p01 = e0b / (e0a + e0b);
    float m1 = fmaxf(s10, s11);
    float e1a = expf(s10 - m1), e1b = expf(s11 - m1);
    float p10 = e1a / (e1a + e1b), p11 = e1b / (e1a + e1b);

    float* ar = g_xq + (size_t)row * DD;
    {
        int d0 = tid, d1 = tid + 128, d2 = tid + 256, d3 = tid + 384;
        ar[d0] = p00 * vb[d0] + p01 * vb[512 + d0];
        ar[d1] = p00 * vb[d1] + p01 * vb[512 + d1];
        ar[d2] = p10 * vb[d2] + p11 * vb[512 + d2];
        ar[d3] = p10 * vb[d3] + p11 * vb[512 + d3];
    }
}

// ---------------------------------------------------------------------------
// Final: out = LN(base + gate[b]*mask*(updc+upda)) with out_ln
// ---------------------------------------------------------------------------
__global__ void final_kernel(const void* __restrict__ mask,
                             const float* __restrict__ og, const float* __restrict__ ob,
                             float* __restrict__ out)
{
    int row = blockIdx.x;
    int b = row >> 12;
    float mk;
    if (g_maskmode == 1)
        mk = ((const unsigned char*)mask)[row] ? 1.f : 0.f;
    else
        mk = (((const int*)mask)[row] != 0) ? 1.f : 0.f;
    float v[4], s = 0.f, s2 = 0.f;
    #pragma unroll
    for (int i = 0; i < 4; i++) {
        int d = threadIdx.x + i * 128;
        size_t idx = (size_t)row * DD + d;
        float val = g_base[idx] + g_gate[b * DD + d] * mk * (g_updc[idx] + g_upda[idx]);
        v[i] = val;
        s += val; s2 += val * val;
    }
    float2 r = block_reduce2_128(s, s2);
    float mean = r.x * (1.f / DD);
    float var  = r.y * (1.f / DD) - mean * mean;
    float inv  = rsqrtf(var + LN_EPS);
    #pragma unroll
    for (int i = 0; i < 4; i++) {
        int d = threadIdx.x + i * 128;
        out[(size_t)row * DD + d] = (v[i] - mean) * inv * og[d] + ob[d];
    }
}

// ---------------------------------------------------------------------------
// Main tiled GEMM:  C[m,n] = act( sum_k A[m,k]*W[n,k] + bias )
// 128x128 tile, BK=16, 256 threads, 8x8 per thread.
// All operand pointers resolved device-side via (ptr,id) pairs.
// AMODE 0: plain A.  AMODE 1: virtual A = [x | ao | x*ao] (K=1536).
// EPI   0: bias[n].  EPI   1: bias[(m>>12)*N + n] (per-batch row bias).
// ---------------------------------------------------------------------------
template<int AMODE, int EPI, bool RELU>
__global__ void __launch_bounds__(256) gemm_tn(
    const float* __restrict__ Ap, int Aid, int lda,
    int A2id,
    const float* __restrict__ Wp, int Wid, int ldb,
    const float* __restrict__ biasp, int biasid,
    int outid,
    int M, int N, int K)
{
    const float* A    = gsel(Ap, Aid);
    const float* A2   = gsel(nullptr, A2id);
    const float* W    = gsel(Wp, Wid);
    const float* bias = gsel(biasp, biasid);
    float* Cout       = gsel(nullptr, outid);

    __shared__ float As[16][128];
    __shared__ float Bs[16][128];
    const int bm = blockIdx.y * 128;
    const int bn = blockIdx.x * 128;
    const int tid = threadIdx.x;
    const int tx = tid & 15;
    const int ty = tid >> 4;

    float acc[8][8];
    #pragma unroll
    for (int i = 0; i < 8; i++)
        #pragma unroll
        for (int j = 0; j < 8; j++) acc[i][j] = 0.f;

    for (int k0 = 0; k0 < K; k0 += 16) {
        #pragma unroll
        for (int rr = 0; rr < 2; rr++) {
            int v   = tid + rr * 256;
            int row = v >> 2;
            int c4  = (v & 3) << 2;
            float4 av;
            if (AMODE == 0) {
                av = *(const float4*)&A[(size_t)(bm + row) * lda + k0 + c4];
            } else {
                int kg = k0 + c4;
                size_t rbase = (size_t)(bm + row) * 512;
                if (kg < 512) {
                    av = *(const float4*)&A[rbase + kg];
                } else if (kg < 1024) {
                    av = *(const float4*)&A2[rbase + (kg - 512)];
                } else {
                    float4 xv = *(const float4*)&A [rbase + (kg - 1024)];
                    float4 ov = *(const float4*)&A2[rbase + (kg - 1024)];
                    av = make_float4(xv.x * ov.x, xv.y * ov.y, xv.z * ov.z, xv.w * ov.w);
                }
            }
            As[c4 + 0][row] = av.x; As[c4 + 1][row] = av.y;
            As[c4 + 2][row] = av.z; As[c4 + 3][row] = av.w;
            float4 bv = *(const float4*)&W[(size_t)(bn + row) * ldb + k0 + c4];
            Bs[c4 + 0][row] = bv.x; Bs[c4 + 1][row] = bv.y;
            Bs[c4 + 2][row] = bv.z; Bs[c4 + 3][row] = bv.w;
        }
        __syncthreads();
        #pragma unroll
        for (int kk = 0; kk < 16; kk++) {
            float4 a0 = *(const float4*)&As[kk][ty * 8];
            float4 a1 = *(const float4*)&As[kk][ty * 8 + 4];
            float4 b0 = *(const float4*)&Bs[kk][tx * 8];
            float4 b1 = *(const float4*)&Bs[kk][tx * 8 + 4];
            float ar[8] = {a0.x, a0.y, a0.z, a0.w, a1.x, a1.y, a1.z, a1.w};
            float br[8] = {b0.x, b0.y, b0.z, b0.w, b1.x, b1.y, b1.z, b1.w};
            #pragma unroll
            for (int i = 0; i < 8; i++)
                #pragma unroll
                for (int j = 0; j < 8; j++)
                    acc[i][j] += ar[i] * br[j];
        }
        __syncthreads();
    }

    #pragma unroll
    for (int i = 0; i < 8; i++) {
        int m = bm + ty * 8 + i;
        int bofs = (EPI == 1) ? ((m >> 12) * N) : 0;
        #pragma unroll
        for (int j4 = 0; j4 < 2; j4++) {
            int n = bn + tx * 8 + j4 * 4;
            float4 o;
            o.x = acc[i][j4 * 4 + 0] + bias[bofs + n + 0];
            o.y = acc[i][j4 * 4 + 1] + bias[bofs + n + 1];
            o.z = acc[i][j4 * 4 + 2] + bias[bofs + n + 2];
            o.w = acc[i][j4 * 4 + 3] + bias[bofs + n + 3];
            if (RELU) {
                o.x = fmaxf(o.x, 0.f); o.y = fmaxf(o.y, 0.f);
                o.z = fmaxf(o.z, 0.f); o.w = fmaxf(o.w, 0.f);
            }
            *(float4*)&Cout[(size_t)m * N + n] = o;
        }
    }
}

// ---------------------------------------------------------------------------
// Launch
// ---------------------------------------------------------------------------
extern "C" void kernel_launch(void* const* d_in, const int* in_sizes, int n_in,
                              void* d_out, int out_size)
{
    const float* x            = (const float*)d_in[0];
    const float* context      = (const float*)d_in[1];
    const void*  pad_mask     = d_in[2];
    const float* film_ln_g    = (const float*)d_in[3];
    const float* film_ln_b    = (const float*)d_in[4];
    const float* film_w       = (const float*)d_in[5];
    const float* film_b       = (const float*)d_in[6];
    const float* concat_w     = (const float*)d_in[7];
    const float* concat_b     = (const float*)d_in[8];
    const float* concat_ln_g  = (const float*)d_in[9];
    const float* concat_ln_b  = (const float*)d_in[10];
    const float* ctx_w1       = (const float*)d_in[11];
    const float* ctx_b1       = (const float*)d_in[12];
    const float* ctx_w2       = (const float*)d_in[13];
    const float* ctx_b2       = (const float*)d_in[14];
    const float* q_ln_g       = (const float*)d_in[15];
    const float* q_ln_b       = (const float*)d_in[16];
    const float* in_proj_w    = (const float*)d_in[17];
    const float* in_proj_b    = (const float*)d_in[18];
    const float* out_proj_w   = (const float*)d_in[19];
    const float* out_proj_b   = (const float*)d_in[20];
    const float* mix_w1       = (const float*)d_in[21];
    const float* mix_b1       = (const float*)d_in[22];
    const float* mix_w2       = (const float*)d_in[23];
    const float* mix_b2       = (const float*)d_in[24];
    const float* out_ln_g     = (const float*)d_in[25];
    const float* out_ln_b     = (const float*)d_in[26];
    const float* gate_w       = (const float*)d_in[27];
    const float* gate_b       = (const float*)d_in[28];
    float* out = (float*)d_out;

    // ---- mask dtype detection ----
    detect_mask_kernel<<<1, 256>>>((const unsigned char*)pad_mask);

    // ---- tiny context-side kernels (outputs selected by id device-side) ----
    small_gemm<<<(BB*1024 + 255) / 256, 256>>>(context, 0, CC, film_w, CC, film_b, /*g_gb*/1,     BB, 1024, CC, 0);
    small_gemm<<<(BB*DD   + 255) / 256, 256>>>(context, 0, CC, gate_w, CC, gate_b, /*g_gate*/2,   BB, DD,   CC, 2);
    small_gemm<<<(BB*HC   + 255) / 256, 256>>>(context, 0, CC, ctx_w1, CC, ctx_b1, /*g_h*/3,      BB, HC,   CC, 1);
    small_gemm<<<(BB*DD   + 255) / 256, 256>>>(context, 0, CC, concat_w + DD, DD + CC, concat_b, /*g_ctxadd*/4, BB, DD, CC, 0);
    small_gemm<<<(BB*1024 + 255) / 256, 256>>>(nullptr, /*g_h*/3, HC, ctx_w2, HC, ctx_b2, /*g_ctxtok*/5, BB, 1024, HC, 0);
    small_gemm<<<(BB*TT*DD + 255) / 256, 256>>>(nullptr, /*g_ctxtok*/5, DD, in_proj_w + (size_t)DD * DD,  DD, in_proj_b + DD,   /*g_k*/6, BB*TT, DD, DD, 0);
    small_gemm<<<(BB*TT*DD + 255) / 256, 256>>>(nullptr, /*g_ctxtok*/5, DD, in_proj_w + (size_t)2*DD*DD,  DD, in_proj_b + 2*DD, /*g_v*/7, BB*TT, DD, DD, 0);
    prep_w1c<<<(1024 * 1536 + 255) / 256, 256>>>(mix_w1);

    // ---- base + x_q (one LN pass over x) ----
    ln_base_kernel<<<BL, 128>>>(x, film_ln_g, film_ln_b, q_ln_g, q_ln_b);

    // ---- q projection: g_q = g_xq @ wq.T + bq ----
    gemm_tn<0, 0, false><<<dim3(DD / 128, BL / 128), 256>>>(
        nullptr, /*A=g_xq*/9, DD, 0, in_proj_w, 0, DD, in_proj_b, 0, /*out=g_q*/10, BL, DD, DD);

    // ---- attention (writes 'a' into g_xq) ----
    attn_kernel<<<BL, 128>>>();

    // ---- out projection: g_ao = a @ out_proj_w.T + b ----
    gemm_tn<0, 0, false><<<dim3(DD / 128, BL / 128), 256>>>(
        nullptr, /*A=g_xq*/9, DD, 0, out_proj_w, 0, DD, out_proj_b, 0, /*out=g_ao*/12, BL, DD, DD);

    // ---- concat branch: relu(x @ concat_w[:, :D].T + ctxadd[b]) ----
    gemm_tn<0, 1, true><<<dim3(DD / 128, BL / 128), 256>>>(
        x, 0, DD, 0, concat_w, 0, DD + CC, nullptr, /*bias=g_ctxadd*/4, /*out=g_updc*/11, BL, DD, DD);
    ln_updc_kernel<<<BL, 128>>>(concat_ln_g, concat_ln_b);

    // ---- mix MLP: hidden = relu([x|ao|x*ao] @ W1c.T + b1) ----
    gemm_tn<1, 0, true><<<dim3(H2 / 128, BL / 128), 256>>>(
        x, 0, DD, /*A2=g_ao*/12, nullptr, /*W=g_w1c*/15, 1536, mix_b1, 0, /*out=g_mixh*/13, BL, H2, 1536);

    // ---- upd_a = hidden @ mix_w2.T + b2 ----
    gemm_tn<0, 0, false><<<dim3(DD / 128, BL / 128), 256>>>(
        nullptr, /*A=g_mixh*/13, H2, 0, mix_w2, 0, H2, mix_b2, 0, /*out=g_upda*/14, BL, DD, H2);

    // ---- final gate + LN ----
    final_kernel<<<BL, 128>>>(pad_mask, out_ln_g, out_ln_b, out);

    (void)in_sizes; (void)n_in; (void)out_size;
}